// round 15
// baseline (speedup 1.0000x reference)
#include <cuda_runtime.h>

#define NT    128
#define GRID  1480                 // 148 SMs x 10 blocks @ 48 regs: one wave
#define STRIDE (GRID * NT)

__device__ double       g_acc;
__device__ unsigned int g_cnt;

__device__ __forceinline__ float frcp(float x) {
    float r; asm("rcp.approx.f32 %0, %1;" : "=f"(r) : "f"(x)); return r;
}

// Compute loss for one pair given its 10 raw values in registers.
__device__ __forceinline__ float pair_loss(const float* b) {
    float x1 = b[0], y1 = b[1], w1 = b[2], h1 = b[3], a1 = b[4];
    float x2 = b[5], y2 = b[6], w2 = b[7], h2 = b[8], a2 = b[9];

    // Box2 local frame, affine-normalized: clip region = [0,1]^2.
    float sf, cf, s2, c2;
    __sincosf(a1 - a2, &sf, &cf);
    __sincosf(a2, &s2, &c2);
    float ddx = x1 - x2, ddy = y1 - y2;
    float dxl = fmaf(ddx, c2, ddy * s2);
    float dyl = fmaf(-ddx, s2, ddy * c2);

    float iw = frcp(w2), ih = frcp(h2);
    float du = fmaf(dxl, iw, 0.5f);
    float dv = fmaf(dyl, ih, 0.5f);
    float hw1 = 0.5f * w1, hh1 = 0.5f * h1;
    float uxn = (hw1 * cf) * iw, uyn = (hw1 * sf) * ih;
    float vxn = -(hh1 * sf) * iw, vyn = (hh1 * cf) * ih;

    float Pu0 = du - uxn - vxn, Pv0 = dv - uyn - vyn;
    float Pu1 = du + uxn - vxn, Pv1 = dv + uyn - vyn;
    float Pu2 = du + uxn + vxn, Pv2 = dv + uyn + vyn;
    float Pu3 = du - uxn + vxn, Pv3 = dv - uyn + vyn;
    float au = uxn + uxn, av = uyn + uyn;
    float bu = vxn + vxn, bv = vyn + vyn;
    float iau = frcp(au), iav = frcp(av);
    float ibu = frcp(bu), ibv = frcp(bv);

    float acc0 = 0.0f, acc1 = 0.0f;
    float fu = 0.0f, fv = 0.0f, pu = 0.0f, pv = 0.0f;

    // Per original edge: u-window [t0,t1] and v-window [slo,shi] in the same
    // t-parameter (shared reciprocals); 4 saturated emission points; connector
    // chords are boundary segments (zero net area on degeneracy).
    #pragma unroll
    for (int k = 0; k < 4; k++) {
        float cu  = (k == 0) ? Pu0 : (k == 1) ? Pu1 : (k == 2) ? Pu2 : Pu3;
        float cv  = (k == 0) ? Pv0 : (k == 1) ? Pv1 : (k == 2) ? Pv2 : Pv3;
        float ru  = (k == 0) ? au  : (k == 1) ? bu  : (k == 2) ? -au : -bu;
        float rv  = (k == 0) ? av  : (k == 1) ? bv  : (k == 2) ? -av : -bv;
        float iru = (k == 0) ? iau : (k == 1) ? ibu : (k == 2) ? -iau : -ibu;
        float irv = (k == 0) ? iav : (k == 1) ? ibv : (k == 2) ? -iav : -ibv;

        float tl = __saturatef(-cu * iru);
        float th = __saturatef(fmaf(-cu, iru, iru));
        float t0 = fminf(tl, th), t1 = fmaxf(tl, th);

        float sv0 = -cv * irv;
        float sv1 = fmaf(-cv, irv, irv);
        float slo = fminf(sv0, sv1), shi = fmaxf(sv0, sv1);

        float tA = fmaxf(t0, slo);
        float tB = fmaxf(fminf(t1, shi), tA);

        float Au = __saturatef(fmaf(t0, ru, cu)), Av = __saturatef(fmaf(t0, rv, cv));
        float Bu = __saturatef(fmaf(tA, ru, cu)), Bv = __saturatef(fmaf(tA, rv, cv));
        float Cu = __saturatef(fmaf(tB, ru, cu)), Cv = __saturatef(fmaf(tB, rv, cv));
        float Du = __saturatef(fmaf(t1, ru, cu)), Dv = __saturatef(fmaf(t1, rv, cv));

        if (k == 0) { fu = Au; fv = Av; }
        else { acc0 = fmaf(pu, Av, acc0); acc0 = fmaf(-pv, Au, acc0); }
        acc1 = fmaf(Au, Bv, acc1); acc1 = fmaf(-Av, Bu, acc1);
        acc0 = fmaf(Bu, Cv, acc0); acc0 = fmaf(-Bv, Cu, acc0);
        acc1 = fmaf(Cu, Dv, acc1); acc1 = fmaf(-Cv, Du, acc1);
        pu = Du; pv = Dv;
    }
    acc0 = fmaf(pu, fv, acc0);
    acc0 = fmaf(-pv, fu, acc0);

    float A2 = w2 * h2, A1 = w1 * h1;
    float area = 0.5f * fabsf(acc0 + acc1) * A2;
    float den = fmaxf(A1 + A2 - area, 1e-10f);
    // -log(clip(area/den, 1e-6)) == min(log(den)-log(area), -log(1e-6))
    float loss = __logf(den) - __logf(area);
    return fminf(loss, 13.815511f);
}

__global__ void __launch_bounds__(NT)
k_loss(const float* __restrict__ pred, const float* __restrict__ tgt,
       float* __restrict__ out, int n) {
    __shared__ double ssum[NT / 32];

    const int tid = threadIdx.x;
    float loss = 0.0f;

    int i = blockIdx.x * NT + tid;
    if (i < n) {
        const float* pp = pred + (size_t)i * 5;
        const float* qq = tgt  + (size_t)i * 5;
        float b0[10];
        #pragma unroll
        for (int j = 0; j < 5; j++) { b0[j] = pp[j]; b0[5 + j] = qq[j]; }

        #pragma unroll 1
        for (;;) {
            bool more = (i + STRIDE) < n;
            // Prefetch next pair's inputs while computing the current pair.
            float b1[10];
            if (more) {
                const float* pn = pp + (size_t)STRIDE * 5;
                const float* qn = qq + (size_t)STRIDE * 5;
                #pragma unroll
                for (int j = 0; j < 5; j++) { b1[j] = pn[j]; b1[5 + j] = qn[j]; }
            }
            loss += pair_loss(b0);
            if (!more) break;
            #pragma unroll
            for (int j = 0; j < 10; j++) b0[j] = b1[j];
            pp += (size_t)STRIDE * 5;
            qq += (size_t)STRIDE * 5;
            i += STRIDE;
        }
    }

    // ---- block reduction ----
    #pragma unroll
    for (int o = 16; o > 0; o >>= 1)
        loss += __shfl_down_sync(0xFFFFFFFFu, loss, o);
    int lane = tid & 31, warp = tid >> 5;
    if (lane == 0) ssum[warp] = (double)loss;
    __syncthreads();

    if (tid == 0) {
        double t = 0.0;
        #pragma unroll
        for (int w = 0; w < NT / 32; w++) t += ssum[w];
        atomicAdd(&g_acc, t);
        __threadfence();
        unsigned int done = atomicAdd(&g_cnt, 1u);
        if (done == (unsigned int)(GRID - 1)) {
            double a = atomicAdd(&g_acc, 0.0);
            out[0] = (float)(a / (double)n);
            atomicExch((unsigned long long*)&g_acc, 0ull);
            atomicExch(&g_cnt, 0u);
        }
    }
}

extern "C" void kernel_launch(void* const* d_in, const int* in_sizes, int n_in,
                              void* d_out, int out_size) {
    const float* pred = (const float*)d_in[0];
    const float* tgt  = (const float*)d_in[1];
    int n = in_sizes[0] / 5;
    k_loss<<<GRID, NT>>>(pred, tgt, (float*)d_out, n);
}